// round 4
// baseline (speedup 1.0000x reference)
#include <cuda_runtime.h>
#include <math.h>

// ---------------------------------------------------------------------------
// KAN_GNN: h = relu(kan1(x)); h = mean_agg(h); h = kan2(h); h = mean_agg(h);
//          out = log_softmax(h)
// kan(x, w, b, c) == [x, x^2, x^3] @ W_eff + b  with
//   W_eff[p*128+i][o] = (p==0 ? w[i][o] : 0) + 0.1 * c[i][o][p]
// Aggregation: pull/gather over device-built CSR (no float atomics).
// edge_index dtype (int32 vs int64) is detected ON DEVICE and normalized to
// int32 src/tgt arrays first — JAX silently downgrades int64->int32, and
// misparsing it as int64 caused the err-717 wild writes in rounds 1-3.
// ---------------------------------------------------------------------------

#define MAX_NODES 100000
#define MAX_EDGES 1600000

__device__ float  g_w1e[384 * 128];
__device__ float  g_w2e[384 * 64];
__device__ float4 g_h1[(size_t)MAX_NODES * 32];   // 128 floats / node
__device__ float4 g_a1[(size_t)MAX_NODES * 32];
__device__ float4 g_h2[(size_t)MAX_NODES * 16];   // 64 floats / node
__device__ int    g_src[MAX_EDGES];
__device__ int    g_tgt[MAX_EDGES];
__device__ int    g_is64;
__device__ int    g_cnt[MAX_NODES];
__device__ int    g_fill[MAX_NODES];
__device__ int    g_rowptr[MAX_NODES + 1];
__device__ int    g_csr[MAX_EDGES];

// ---------------------------------------------------------------------------
// Edge dtype detection + normalization
// ---------------------------------------------------------------------------
__global__ void detect_dtype(const int* __restrict__ buf) {
    // int64 values in [0, 2^31): every odd 32-bit word (high half) is 0.
    // int32: odd words are random node ids, virtually never all zero.
    if (threadIdx.x == 0 && blockIdx.x == 0) {
        int any = 0;
        for (int i = 1; i < 256; i += 2) any |= buf[i];
        g_is64 = (any == 0) ? 1 : 0;
    }
}

__global__ void convert_edges(const void* __restrict__ ei, int E) {
    int e = blockIdx.x * blockDim.x + threadIdx.x;
    if (e >= E) return;
    int s, t;
    if (g_is64) {
        const long long* p = (const long long*)ei;
        s = (int)p[e];
        t = (int)p[e + E];
    } else {
        const int* p = (const int*)ei;
        s = p[e];
        t = p[e + E];
    }
    g_src[e] = s;
    g_tgt[e] = t;
}

// ---------------------------------------------------------------------------
__global__ void fuse_weights(const float* __restrict__ w1, const float* __restrict__ c1,
                             const float* __restrict__ w2, const float* __restrict__ c2) {
    int idx = blockIdx.x * blockDim.x + threadIdx.x;
    const int T1 = 384 * 128;
    const int T2 = 384 * 64;
    if (idx < T1) {
        int k = idx >> 7, o = idx & 127;   // k in [0,384), o in [0,128)
        int i = k & 127, p = k >> 7;       // base feature, power index
        float v = 0.1f * c1[(i * 128 + o) * 3 + p];
        if (p == 0) v += w1[i * 128 + o];
        g_w1e[idx] = v;
    } else if (idx < T1 + T2) {
        int j = idx - T1;
        int k = j / 64, o = j % 64;
        int i = k & 127, p = k >> 7;
        float v = 0.1f * c2[(i * 64 + o) * 3 + p];
        if (p == 0) v += w2[i * 64 + o];
        g_w2e[j] = v;
    }
}

// ---------------------------------------------------------------------------
// Tiled GEMM: Out[N x BN] = Aug(X)[N x 384] @ Weff[384 x BN] + bias (opt relu)
// Aug(X)[n][p*128+i] = X[n][i]^(p+1), computed on the fly during A-tile load.
// BM=128, BK=16, 256 threads, TM=8 x TN=(BN/16) register tile per thread.
// ---------------------------------------------------------------------------
template <int LAYER>
__global__ void kan_gemm(const float* __restrict__ Xparam,
                         const float* __restrict__ bias, int N) {
    const int BN = (LAYER == 1) ? 128 : 64;
    const int BM = 128, BK = 16;
    const int TM = 8, TN = BN / 16;
    __shared__ float As[BK * 129];   // [kk][m], padded row stride 129
    __shared__ float Bs[BK * BN];    // [kk][o]

    const float* X    = (LAYER == 1) ? Xparam : (const float*)g_a1;
    const float* Weff = (LAYER == 1) ? g_w1e : g_w2e;
    float*       Out  = (LAYER == 1) ? (float*)g_h1 : (float*)g_h2;

    int tid = threadIdx.x;
    int ty = tid >> 4, tx = tid & 15;
    int rowBase = blockIdx.x * BM;

    float acc[TM][TN];
#pragma unroll
    for (int i = 0; i < TM; i++)
#pragma unroll
        for (int j = 0; j < TN; j++) acc[i][j] = 0.f;

    for (int k0 = 0; k0 < 384; k0 += BK) {
        int p = k0 >> 7;       // power index for this k-block (BK divides 128)
        int i0 = k0 & 127;
        // load A tile: 128x16, 8 scalars per thread
#pragma unroll
        for (int l = 0; l < 8; l++) {
            int idx = tid + l * 256;
            int m = idx >> 4, kk = idx & 15;
            int n = rowBase + m;
            float v = 0.f;
            if (n < N) {
                float xv = X[(size_t)n * 128 + i0 + kk];
                v = (p == 0) ? xv : (p == 1) ? xv * xv : xv * xv * xv;
            }
            As[kk * 129 + m] = v;
        }
        // load B tile: 16 x BN
#pragma unroll
        for (int l = 0; l < (BK * BN) / 256; l++) {
            int idx = tid + l * 256;
            int kk = idx / BN, o = idx % BN;
            Bs[kk * BN + o] = Weff[(k0 + kk) * BN + o];
        }
        __syncthreads();
#pragma unroll
        for (int kk = 0; kk < BK; kk++) {
            float a[TM], b[TN];
#pragma unroll
            for (int i = 0; i < TM; i++) a[i] = As[kk * 129 + ty * TM + i];
#pragma unroll
            for (int j = 0; j < TN; j++) b[j] = Bs[kk * BN + tx * TN + j];
#pragma unroll
            for (int i = 0; i < TM; i++)
#pragma unroll
                for (int j = 0; j < TN; j++) acc[i][j] += a[i] * b[j];
        }
        __syncthreads();
    }

#pragma unroll
    for (int i = 0; i < TM; i++) {
        int n = rowBase + ty * TM + i;
        if (n < N) {
#pragma unroll
            for (int j = 0; j < TN; j++) {
                int o = tx * TN + j;
                float v = acc[i][j] + bias[o];
                if (LAYER == 1) v = fmaxf(v, 0.f);
                Out[(size_t)n * BN + o] = v;
            }
        }
    }
}

// ---------------------------------------------------------------------------
// CSR construction (all edge-derived indices bounds-guarded)
// ---------------------------------------------------------------------------
__global__ void zero_int2(int N) {
    int i = blockIdx.x * blockDim.x + threadIdx.x;
    if (i < N) { g_cnt[i] = 0; g_fill[i] = 0; }
}

__global__ void hist_kernel(int E, int N) {
    int e = blockIdx.x * blockDim.x + threadIdx.x;
    if (e < E) {
        int t = g_tgt[e];
        if ((unsigned)t < (unsigned)N) atomicAdd(&g_cnt[t], 1);
    }
}

// single-block scan: g_rowptr[0]=0, g_rowptr[i+1] = sum g_cnt[0..i]
__global__ void scan_kernel(int n) {
    __shared__ int sh[1024];
    __shared__ int carry_s;
    if (threadIdx.x == 0) { carry_s = 0; g_rowptr[0] = 0; }
    __syncthreads();
    for (int base = 0; base < n; base += 1024) {
        int i = base + (int)threadIdx.x;
        int v = (i < n) ? g_cnt[i] : 0;
        sh[threadIdx.x] = v;
        __syncthreads();
        for (int off = 1; off < 1024; off <<= 1) {
            int t = (threadIdx.x >= (unsigned)off) ? sh[threadIdx.x - off] : 0;
            __syncthreads();
            sh[threadIdx.x] += t;
            __syncthreads();
        }
        if (i < n) g_rowptr[i + 1] = carry_s + sh[threadIdx.x];
        __syncthreads();
        if (threadIdx.x == 1023) carry_s += sh[1023];
        __syncthreads();
    }
}

__global__ void build_csr(int E, int N) {
    int e = blockIdx.x * blockDim.x + threadIdx.x;
    if (e < E) {
        int t = g_tgt[e];
        int s = g_src[e];
        if ((unsigned)t < (unsigned)N && (unsigned)s < (unsigned)N) {
            int pos = g_rowptr[t] + atomicAdd(&g_fill[t], 1);
            if ((unsigned)pos < (unsigned)MAX_EDGES) g_csr[pos] = s;
        }
    }
}

// ---------------------------------------------------------------------------
// gather-mean 1: g_a1[n][:] = mean over incoming neighbors s of g_h1[s][:]
// 32-lane group per node, each lane owns one float4 (128 floats total).
// ---------------------------------------------------------------------------
__global__ void gather_mean1(int N) {
    int g = blockIdx.x * 8 + ((int)threadIdx.x >> 5);
    int lane = (int)threadIdx.x & 31;
    if (g >= N) return;
    int beg = g_rowptr[g], end = g_rowptr[g + 1];
    float4 acc = make_float4(0.f, 0.f, 0.f, 0.f);
    for (int e = beg; e < end; e++) {
        int s = g_csr[e];
        float4 v = g_h1[(size_t)s * 32 + lane];
        acc.x += v.x; acc.y += v.y; acc.z += v.z; acc.w += v.w;
    }
    float inv = 1.f / (float)max(end - beg, 1);
    acc.x *= inv; acc.y *= inv; acc.z *= inv; acc.w *= inv;
    g_a1[(size_t)g * 32 + lane] = acc;
}

// gather-mean 2 + log_softmax over 64 features; 16-lane group per node.
__global__ void gather_mean_lsm(float4* __restrict__ Out, int N) {
    int g = blockIdx.x * 16 + ((int)threadIdx.x >> 4);
    int lane = (int)threadIdx.x & 15;
    if (g >= N) return;
    int beg = g_rowptr[g], end = g_rowptr[g + 1];
    float4 acc = make_float4(0.f, 0.f, 0.f, 0.f);
    for (int e = beg; e < end; e++) {
        int s = g_csr[e];
        float4 v = g_h2[(size_t)s * 16 + lane];
        acc.x += v.x; acc.y += v.y; acc.z += v.z; acc.w += v.w;
    }
    float inv = 1.f / (float)max(end - beg, 1);
    acc.x *= inv; acc.y *= inv; acc.z *= inv; acc.w *= inv;

    // log_softmax across the 16-lane group (64 values)
    float m = fmaxf(fmaxf(acc.x, acc.y), fmaxf(acc.z, acc.w));
#pragma unroll
    for (int off = 8; off; off >>= 1) m = fmaxf(m, __shfl_xor_sync(0xffffffffu, m, off));
    float s = expf(acc.x - m) + expf(acc.y - m) + expf(acc.z - m) + expf(acc.w - m);
#pragma unroll
    for (int off = 8; off; off >>= 1) s += __shfl_xor_sync(0xffffffffu, s, off);
    float lse = m + logf(s);
    acc.x -= lse; acc.y -= lse; acc.z -= lse; acc.w -= lse;
    Out[(size_t)g * 16 + lane] = acc;
}

// ---------------------------------------------------------------------------
extern "C" void kernel_launch(void* const* d_in, const int* in_sizes, int n_in,
                              void* d_out, int out_size) {
    const float* x  = (const float*)d_in[0];
    const void*  ei = d_in[1];
    const float* w1 = (const float*)d_in[2];
    const float* b1 = (const float*)d_in[3];
    const float* c1 = (const float*)d_in[4];
    const float* w2 = (const float*)d_in[5];
    const float* b2 = (const float*)d_in[6];
    const float* c2 = (const float*)d_in[7];
    float4* out     = (float4*)d_out;

    int N = in_sizes[0] / 128;
    int E = in_sizes[1] / 2;

    // edge dtype normalization
    detect_dtype<<<1, 32>>>((const int*)ei);
    convert_edges<<<(E + 255) / 256, 256>>>(ei, E);

    // CSR build
    zero_int2<<<(N + 255) / 256, 256>>>(N);
    hist_kernel<<<(E + 255) / 256, 256>>>(E, N);
    scan_kernel<<<1, 1024>>>(N);
    build_csr<<<(E + 255) / 256, 256>>>(E, N);

    // weights + layer 1
    fuse_weights<<<(384 * 128 + 384 * 64 + 255) / 256, 256>>>(w1, c1, w2, c2);
    kan_gemm<1><<<(N + 127) / 128, 256>>>(x, b1, N);

    // aggregate 1 (mean)
    gather_mean1<<<(N + 7) / 8, 256>>>(N);

    // layer 2
    kan_gemm<2><<<(N + 127) / 128, 256>>>(nullptr, b2, N);

    // aggregate 2 (mean) + log_softmax, straight into d_out
    gather_mean_lsm<<<(N + 15) / 16, 256>>>(out, N);
}

// round 6
// speedup vs baseline: 2.0059x; 2.0059x over previous
#include <cuda_runtime.h>
#include <cuda_bf16.h>
#include <math.h>
#include <stdint.h>

// ---------------------------------------------------------------------------
// KAN_GNN: GEMMs on mma.sync bf16x2 (fp32-class precision, baseline PTX
// features only -- harness targets compute_103 so tcgen05/'a' features are
// unavailable). CSR pull aggregation, fused mean+log_softmax epilogue.
// kan(x,w,b,c) == [x,x^2,x^3] @ W_eff + b,
//   W_eff[p*128+i][o] = (p==0 ? w[i][o] : 0) + 0.1*c[i][o][p]
// ---------------------------------------------------------------------------

#define MAX_NODES 100000
#define MAX_EDGES 1600000

__device__ __nv_bfloat16 g_w1hi[128 * 384];  // W_eff^T hi, [o][k]
__device__ __nv_bfloat16 g_w1lo[128 * 384];
__device__ __nv_bfloat16 g_w2hi[64 * 384];
__device__ __nv_bfloat16 g_w2lo[64 * 384];
__device__ float4 g_h1[(size_t)MAX_NODES * 32];   // 128 floats / node
__device__ float4 g_a1[(size_t)MAX_NODES * 32];
__device__ float4 g_h2[(size_t)MAX_NODES * 16];   // 64 floats / node
__device__ int    g_src[MAX_EDGES];
__device__ int    g_tgt[MAX_EDGES];
__device__ int    g_is64;
__device__ int    g_cnt[MAX_NODES];
__device__ int    g_fill[MAX_NODES];
__device__ int    g_rowptr[MAX_NODES + 1];
__device__ int    g_csr[MAX_EDGES];
__device__ int    g_blk[128];

// ---------------------------------------------------------------------------
// helpers
// ---------------------------------------------------------------------------
__device__ __forceinline__ uint32_t smem_u32(const void* p) {
    uint32_t a;
    asm("{ .reg .u64 t; cvta.to.shared.u64 t, %1; cvt.u32.u64 %0, t; }" : "=r"(a) : "l"(p));
    return a;
}
__device__ __forceinline__ void ldsm4(uint32_t r[4], uint32_t addr) {
    asm volatile("ldmatrix.sync.aligned.m8n8.x4.shared.b16 {%0,%1,%2,%3}, [%4];"
                 : "=r"(r[0]), "=r"(r[1]), "=r"(r[2]), "=r"(r[3]) : "r"(addr));
}
__device__ __forceinline__ void mma16816(float d[4], const uint32_t a[4], const uint32_t b[2]) {
    asm volatile(
        "mma.sync.aligned.m16n8k16.row.col.f32.bf16.bf16.f32 "
        "{%0,%1,%2,%3}, {%4,%5,%6,%7}, {%8,%9}, {%0,%1,%2,%3};"
        : "+f"(d[0]), "+f"(d[1]), "+f"(d[2]), "+f"(d[3])
        : "r"(a[0]), "r"(a[1]), "r"(a[2]), "r"(a[3]), "r"(b[0]), "r"(b[1]));
}
// split two floats into packed bf16 hi pair + bf16 lo pair
__device__ __forceinline__ void split2(float x, float y, uint32_t& hi, uint32_t& lo) {
    __nv_bfloat16 hx = __float2bfloat16_rn(x), hy = __float2bfloat16_rn(y);
    float rx = x - __bfloat162float(hx), ry = y - __bfloat162float(hy);
    __nv_bfloat16 lx = __float2bfloat16_rn(rx), ly = __float2bfloat16_rn(ry);
    hi = ((uint32_t)__bfloat16_as_ushort(hy) << 16) | (uint32_t)__bfloat16_as_ushort(hx);
    lo = ((uint32_t)__bfloat16_as_ushort(ly) << 16) | (uint32_t)__bfloat16_as_ushort(lx);
}

// ---------------------------------------------------------------------------
// Edge dtype detection + fused convert/histogram
// ---------------------------------------------------------------------------
__global__ void detect_dtype(const int* __restrict__ buf) {
    if (threadIdx.x == 0 && blockIdx.x == 0) {
        int any = 0;
        for (int i = 1; i < 256; i += 2) any |= buf[i];
        g_is64 = (any == 0) ? 1 : 0;
    }
}

__global__ void zero_int2(int N) {
    int i = blockIdx.x * blockDim.x + threadIdx.x;
    if (i < N) { g_cnt[i] = 0; g_fill[i] = 0; }
}

__global__ void convert_hist(const void* __restrict__ ei, int E, int N) {
    int e = blockIdx.x * blockDim.x + threadIdx.x;
    if (e >= E) return;
    int s, t;
    if (g_is64) {
        const long long* p = (const long long*)ei;
        s = (int)p[e]; t = (int)p[e + E];
    } else {
        const int* p = (const int*)ei;
        s = p[e]; t = p[e + E];
    }
    g_src[e] = s;
    g_tgt[e] = t;
    if ((unsigned)t < (unsigned)N) atomicAdd(&g_cnt[t], 1);
}

// ---------------------------------------------------------------------------
// multi-block scan: rowptr[i+1] = sum cnt[0..i]
// ---------------------------------------------------------------------------
__global__ void scan_partials(int n) {
    __shared__ int sh[1024];
    int i = blockIdx.x * 1024 + threadIdx.x;
    sh[threadIdx.x] = (i < n) ? g_cnt[i] : 0;
    __syncthreads();
    for (int off = 1; off < 1024; off <<= 1) {
        int t = (threadIdx.x >= (unsigned)off) ? sh[threadIdx.x - off] : 0;
        __syncthreads();
        sh[threadIdx.x] += t;
        __syncthreads();
    }
    if (i < n) g_rowptr[i + 1] = sh[threadIdx.x];
    if (threadIdx.x == 1023) g_blk[blockIdx.x] = sh[1023];
}

__global__ void scan_blocks(int nb) {
    if (threadIdx.x == 0 && blockIdx.x == 0) {
        int s = 0;
        for (int b = 0; b < nb; b++) { int t = g_blk[b]; g_blk[b] = s; s += t; }
        g_rowptr[0] = 0;
    }
}

__global__ void add_offsets(int n) {
    int i = blockIdx.x * 1024 + threadIdx.x;
    if (i < n) g_rowptr[i + 1] += g_blk[blockIdx.x];
}

__global__ void build_csr(int E, int N) {
    int e = blockIdx.x * blockDim.x + threadIdx.x;
    if (e < E) {
        int t = g_tgt[e];
        int s = g_src[e];
        if ((unsigned)t < (unsigned)N && (unsigned)s < (unsigned)N) {
            int pos = g_rowptr[t] + atomicAdd(&g_fill[t], 1);
            if ((unsigned)pos < (unsigned)MAX_EDGES) g_csr[pos] = s;
        }
    }
}

// ---------------------------------------------------------------------------
// fused weights, transposed to [o][k], split into bf16 hi/lo
// ---------------------------------------------------------------------------
__global__ void fuse_weights_t(const float* __restrict__ w1, const float* __restrict__ c1,
                               const float* __restrict__ w2, const float* __restrict__ c2) {
    int idx = blockIdx.x * blockDim.x + threadIdx.x;
    const int T1 = 384 * 128;
    const int T2 = 384 * 64;
    if (idx < T1) {
        int k = idx >> 7, o = idx & 127;
        int i = k & 127, p = k >> 7;
        float v = 0.1f * c1[(i * 128 + o) * 3 + p];
        if (p == 0) v += w1[i * 128 + o];
        __nv_bfloat16 h = __float2bfloat16_rn(v);
        g_w1hi[o * 384 + k] = h;
        g_w1lo[o * 384 + k] = __float2bfloat16_rn(v - __bfloat162float(h));
    } else if (idx < T1 + T2) {
        int j = idx - T1;
        int k = j >> 6, o = j & 63;
        int i = k & 127, p = k >> 7;
        float v = 0.1f * c2[(i * 64 + o) * 3 + p];
        if (p == 0) v += w2[i * 64 + o];
        __nv_bfloat16 h = __float2bfloat16_rn(v);
        g_w2hi[o * 384 + k] = h;
        g_w2lo[o * 384 + k] = __float2bfloat16_rn(v - __bfloat162float(h));
    }
}

// ---------------------------------------------------------------------------
// mma.sync bf16x2 GEMM: Out[128-tile x BN] = Aug(X)[tile x 384] @ Weff + bias.
// BK=32, double-buffered SMEM (pad-8 bf16 rows), 8 warps = 4(M) x 2(N).
// acc += Ahi*Bhi + Ahi*Blo + Alo*Bhi (fp32 accumulate in MMA).
// ---------------------------------------------------------------------------
template <int BN>
__global__ void __launch_bounds__(256) kan_gemm_mma(const float* __restrict__ Xp,
                                                    const float* __restrict__ bias, int N) {
    const int NT = BN / 16;                       // n8-tiles per warp
    const uint32_t ASZ = 128 * 40 * 2;            // bf16 tile, stride 40
    const uint32_t BSZ = (uint32_t)BN * 40 * 2;
    const uint32_t AHo = 0, BHo = 2 * ASZ;
    const uint32_t SBUF = 2 * ASZ + 2 * BSZ;

    extern __shared__ __align__(128) char smem[];
    uint32_t sb = smem_u32(smem);
    int tid = threadIdx.x, lane = tid & 31, wid = tid >> 5;
    int warp_m = wid & 3, warp_n = wid >> 2;
    int rowBase = blockIdx.x * 128;

    const float4* X4 = (BN == 128) ? (const float4*)Xp : g_a1;
    const __nv_bfloat16* WHp = (BN == 128) ? g_w1hi : g_w2hi;
    const __nv_bfloat16* WLp = (BN == 128) ? g_w1lo : g_w2lo;
    float* Out = (BN == 128) ? (float*)g_h1 : (float*)g_h2;

    // ---- producer indexing: thread -> (row, 16-col half) ----
    int rowl = tid >> 1, half = tid & 1;
    int nrow = rowBase + rowl;
    bool bact = rowl < BN;

    float4 xa[4];
    uint4 wh0, wh1, wl0, wl1;

    auto loadA = [&](int c) {
        int p = c >> 2;
        int i0 = (c & 3) * 32 + half * 16;
        if (nrow < N) {
            const float4* ptr = X4 + (size_t)nrow * 32 + (i0 >> 2);
            xa[0] = ptr[0]; xa[1] = ptr[1]; xa[2] = ptr[2]; xa[3] = ptr[3];
        } else {
            xa[0] = xa[1] = xa[2] = xa[3] = make_float4(0.f, 0.f, 0.f, 0.f);
        }
        if (p == 1) {
#pragma unroll
            for (int j = 0; j < 4; j++) {
                xa[j].x *= xa[j].x; xa[j].y *= xa[j].y;
                xa[j].z *= xa[j].z; xa[j].w *= xa[j].w;
            }
        } else if (p == 2) {
#pragma unroll
            for (int j = 0; j < 4; j++) {
                xa[j].x = xa[j].x * xa[j].x * xa[j].x;
                xa[j].y = xa[j].y * xa[j].y * xa[j].y;
                xa[j].z = xa[j].z * xa[j].z * xa[j].z;
                xa[j].w = xa[j].w * xa[j].w * xa[j].w;
            }
        }
    };
    auto loadB = [&](int c) {
        if (!bact) return;
        size_t off = (size_t)rowl * 384 + c * 32 + half * 16;
        wh0 = *(const uint4*)(WHp + off); wh1 = *(const uint4*)(WHp + off + 8);
        wl0 = *(const uint4*)(WLp + off); wl1 = *(const uint4*)(WLp + off + 8);
    };
    auto sts = [&](int buf) {
        char* abase = smem + buf * SBUF + AHo + rowl * 80 + half * 32;
#pragma unroll
        for (int j = 0; j < 4; j++) {
            uint32_t h0, l0, h1, l1;
            split2(xa[j].x, xa[j].y, h0, l0);
            split2(xa[j].z, xa[j].w, h1, l1);
            *(uint2*)(abase + j * 8) = make_uint2(h0, h1);
            *(uint2*)(abase + ASZ + j * 8) = make_uint2(l0, l1);
        }
        if (bact) {
            char* bbase = smem + buf * SBUF + BHo + rowl * 80 + half * 32;
            *(uint4*)(bbase) = wh0;
            *(uint4*)(bbase + 16) = wh1;
            *(uint4*)(bbase + BSZ) = wl0;
            *(uint4*)(bbase + BSZ + 16) = wl1;
        }
    };

    // ---- consumer: ldmatrix lane offsets ----
    int lr = lane & 7, ls = lane >> 3;
    int a_row = lr + ((ls & 1) << 3);
    int a_k = (ls >> 1) << 3;
    int b_row = lr + ((ls >> 1) << 3);
    int b_k = (ls & 1) << 3;

    float acc[2][NT][4];
#pragma unroll
    for (int i = 0; i < 2; i++)
#pragma unroll
        for (int j = 0; j < NT; j++)
#pragma unroll
            for (int q = 0; q < 4; q++) acc[i][j][q] = 0.f;

    auto compute = [&](int buf) {
        uint32_t base = sb + buf * SBUF;
#pragma unroll
        for (int ks = 0; ks < 32; ks += 16) {
            uint32_t ah[2][4], al[2][4];
#pragma unroll
            for (int i = 0; i < 2; i++) {
                uint32_t ad = base + AHo + (uint32_t)(warp_m * 32 + i * 16 + a_row) * 80 +
                              (uint32_t)(ks + a_k) * 2;
                ldsm4(ah[i], ad);
                ldsm4(al[i], ad + ASZ);
            }
            uint32_t bh[NT][2], bl[NT][2];
#pragma unroll
            for (int j2 = 0; j2 < NT / 2; j2++) {
                uint32_t bd = base + BHo +
                              (uint32_t)(warp_n * (BN / 2) + j2 * 16 + b_row) * 80 +
                              (uint32_t)(ks + b_k) * 2;
                uint32_t t[4];
                ldsm4(t, bd);
                bh[2 * j2][0] = t[0]; bh[2 * j2][1] = t[1];
                bh[2 * j2 + 1][0] = t[2]; bh[2 * j2 + 1][1] = t[3];
                ldsm4(t, bd + BSZ);
                bl[2 * j2][0] = t[0]; bl[2 * j2][1] = t[1];
                bl[2 * j2 + 1][0] = t[2]; bl[2 * j2 + 1][1] = t[3];
            }
#pragma unroll
            for (int i = 0; i < 2; i++)
#pragma unroll
                for (int j = 0; j < NT; j++) {
                    mma16816(acc[i][j], ah[i], bh[j]);
                    mma16816(acc[i][j], ah[i], bl[j]);
                    mma16816(acc[i][j], al[i], bh[j]);
                }
        }
    };

    // ---- pipelined main loop over 12 K-chunks ----
    loadA(0); loadB(0);
    for (int c = 0; c < 12; c++) {
        int buf = c & 1;
        sts(buf);
        __syncthreads();
        if (c < 11) { loadA(c + 1); loadB(c + 1); }
        compute(buf);
        __syncthreads();
    }

    // ---- epilogue: bias (+relu), float2 stores ----
    int g = lane >> 2, t4 = lane & 3;
#pragma unroll
    for (int i = 0; i < 2; i++) {
        int m0 = rowBase + warp_m * 32 + i * 16 + g;
#pragma unroll
        for (int j = 0; j < NT; j++) {
            int col = warp_n * (BN / 2) + j * 8 + t4 * 2;
            float bx = bias[col], by = bias[col + 1];
            float v0 = acc[i][j][0] + bx, v1 = acc[i][j][1] + by;
            float v2 = acc[i][j][2] + bx, v3 = acc[i][j][3] + by;
            if (BN == 128) {
                v0 = fmaxf(v0, 0.f); v1 = fmaxf(v1, 0.f);
                v2 = fmaxf(v2, 0.f); v3 = fmaxf(v3, 0.f);
            }
            if (m0 < N) *(float2*)(Out + (size_t)m0 * BN + col) = make_float2(v0, v1);
            if (m0 + 8 < N) *(float2*)(Out + (size_t)(m0 + 8) * BN + col) = make_float2(v2, v3);
        }
    }
}

// ---------------------------------------------------------------------------
// gather-mean 1: g_a1[n][:] = mean over incoming neighbors s of g_h1[s][:]
// ---------------------------------------------------------------------------
__global__ void gather_mean1(int N) {
    int g = blockIdx.x * 8 + ((int)threadIdx.x >> 5);
    int lane = (int)threadIdx.x & 31;
    if (g >= N) return;
    int beg = g_rowptr[g], end = g_rowptr[g + 1];
    float4 acc = make_float4(0.f, 0.f, 0.f, 0.f);
    for (int e = beg; e < end; e++) {
        int s = g_csr[e];
        float4 v = g_h1[(size_t)s * 32 + lane];
        acc.x += v.x; acc.y += v.y; acc.z += v.z; acc.w += v.w;
    }
    float inv = 1.f / (float)max(end - beg, 1);
    acc.x *= inv; acc.y *= inv; acc.z *= inv; acc.w *= inv;
    g_a1[(size_t)g * 32 + lane] = acc;
}

// gather-mean 2 + log_softmax over 64 features; 16-lane group per node.
__global__ void gather_mean_lsm(float4* __restrict__ Out, int N) {
    int g = blockIdx.x * 16 + ((int)threadIdx.x >> 4);
    int lane = (int)threadIdx.x & 15;
    if (g >= N) return;
    int beg = g_rowptr[g], end = g_rowptr[g + 1];
    float4 acc = make_float4(0.f, 0.f, 0.f, 0.f);
    for (int e = beg; e < end; e++) {
        int s = g_csr[e];
        float4 v = g_h2[(size_t)s * 16 + lane];
        acc.x += v.x; acc.y += v.y; acc.z += v.z; acc.w += v.w;
    }
    float inv = 1.f / (float)max(end - beg, 1);
    acc.x *= inv; acc.y *= inv; acc.z *= inv; acc.w *= inv;

    float m = fmaxf(fmaxf(acc.x, acc.y), fmaxf(acc.z, acc.w));
#pragma unroll
    for (int off = 8; off; off >>= 1) m = fmaxf(m, __shfl_xor_sync(0xffffffffu, m, off));
    float s = expf(acc.x - m) + expf(acc.y - m) + expf(acc.z - m) + expf(acc.w - m);
#pragma unroll
    for (int off = 8; off; off >>= 1) s += __shfl_xor_sync(0xffffffffu, s, off);
    float lse = m + logf(s);
    acc.x -= lse; acc.y -= lse; acc.z -= lse; acc.w -= lse;
    Out[(size_t)g * 16 + lane] = acc;
}

// ---------------------------------------------------------------------------
extern "C" void kernel_launch(void* const* d_in, const int* in_sizes, int n_in,
                              void* d_out, int out_size) {
    const float* x  = (const float*)d_in[0];
    const void*  ei = d_in[1];
    const float* w1 = (const float*)d_in[2];
    const float* b1 = (const float*)d_in[3];
    const float* c1 = (const float*)d_in[4];
    const float* w2 = (const float*)d_in[5];
    const float* b2 = (const float*)d_in[6];
    const float* c2 = (const float*)d_in[7];
    float4* out     = (float4*)d_out;

    int N = in_sizes[0] / 128;
    int E = in_sizes[1] / 2;

    // dynamic smem: 2 * (2*10240 + 2*BN*80) bytes
    const int SMEM1 = 2 * (2 * 10240 + 2 * 128 * 80);  // 81920
    const int SMEM2 = 2 * (2 * 10240 + 2 * 64 * 80);   // 61440
    cudaFuncSetAttribute(kan_gemm_mma<128>, cudaFuncAttributeMaxDynamicSharedMemorySize, SMEM1);
    cudaFuncSetAttribute(kan_gemm_mma<64>,  cudaFuncAttributeMaxDynamicSharedMemorySize, SMEM2);

    // edge normalization + CSR
    zero_int2<<<(N + 255) / 256, 256>>>(N);
    detect_dtype<<<1, 32>>>((const int*)ei);
    convert_hist<<<(E + 255) / 256, 256>>>(ei, E, N);
    int nb = (N + 1023) / 1024;
    scan_partials<<<nb, 1024>>>(N);
    scan_blocks<<<1, 32>>>(nb);
    add_offsets<<<nb, 1024>>>(N);
    build_csr<<<(E + 255) / 256, 256>>>(E, N);

    // weights + layer 1
    fuse_weights_t<<<(384 * 128 + 384 * 64 + 255) / 256, 256>>>(w1, c1, w2, c2);
    int tiles = (N + 127) / 128;
    kan_gemm_mma<128><<<tiles, 256, SMEM1>>>(x, b1, N);

    // aggregate 1 (mean)
    gather_mean1<<<(N + 7) / 8, 256>>>(N);

    // layer 2
    kan_gemm_mma<64><<<tiles, 256, SMEM2>>>(nullptr, b2, N);

    // aggregate 2 (mean) + log_softmax, straight into d_out
    gather_mean_lsm<<<(N + 15) / 16, 256>>>(out, N);
}

// round 7
// speedup vs baseline: 2.1818x; 1.0877x over previous
#include <cuda_runtime.h>
#include <cuda_bf16.h>
#include <math.h>
#include <stdint.h>

// ---------------------------------------------------------------------------
// KAN_GNN: GEMMs on mma.sync bf16x2 (fp32-class precision; compute_103 target
// so no tcgen05). CSR pull aggregation (unrolled, MLP=4), fused
// mean+log_softmax epilogue, CSR build overlapped with GEMM1 via fork-join.
// kan(x,w,b,c) == [x,x^2,x^3] @ W_eff + b,
//   W_eff[p*128+i][o] = (p==0 ? w[i][o] : 0) + 0.1*c[i][o][p]
// ---------------------------------------------------------------------------

#define MAX_NODES 100000
#define MAX_EDGES 1600000

__device__ __nv_bfloat16 g_w1hi[128 * 384];  // W_eff^T hi, [o][k]
__device__ __nv_bfloat16 g_w1lo[128 * 384];
__device__ __nv_bfloat16 g_w2hi[64 * 384];
__device__ __nv_bfloat16 g_w2lo[64 * 384];
__device__ float4 g_h1[(size_t)MAX_NODES * 32];   // 128 floats / node
__device__ float4 g_a1[(size_t)MAX_NODES * 32];
__device__ float4 g_h2[(size_t)MAX_NODES * 16];   // 64 floats / node
__device__ int    g_src[MAX_EDGES];
__device__ int    g_tgt[MAX_EDGES];
__device__ int    g_is64;
__device__ int    g_cnt[MAX_NODES];
__device__ int    g_fill[MAX_NODES];
__device__ int    g_rowptr[MAX_NODES + 1];
__device__ int    g_csr[MAX_EDGES];
__device__ int    g_blk[128];

// ---------------------------------------------------------------------------
// helpers
// ---------------------------------------------------------------------------
__device__ __forceinline__ uint32_t smem_u32(const void* p) {
    uint32_t a;
    asm("{ .reg .u64 t; cvta.to.shared.u64 t, %1; cvt.u32.u64 %0, t; }" : "=r"(a) : "l"(p));
    return a;
}
__device__ __forceinline__ void ldsm4(uint32_t r[4], uint32_t addr) {
    asm volatile("ldmatrix.sync.aligned.m8n8.x4.shared.b16 {%0,%1,%2,%3}, [%4];"
                 : "=r"(r[0]), "=r"(r[1]), "=r"(r[2]), "=r"(r[3]) : "r"(addr));
}
__device__ __forceinline__ void mma16816(float d[4], const uint32_t a[4], const uint32_t b[2]) {
    asm volatile(
        "mma.sync.aligned.m16n8k16.row.col.f32.bf16.bf16.f32 "
        "{%0,%1,%2,%3}, {%4,%5,%6,%7}, {%8,%9}, {%0,%1,%2,%3};"
        : "+f"(d[0]), "+f"(d[1]), "+f"(d[2]), "+f"(d[3])
        : "r"(a[0]), "r"(a[1]), "r"(a[2]), "r"(a[3]), "r"(b[0]), "r"(b[1]));
}
// split two floats into packed bf16 hi pair + bf16 lo pair
__device__ __forceinline__ void split2(float x, float y, uint32_t& hi, uint32_t& lo) {
    __nv_bfloat16 hx = __float2bfloat16_rn(x), hy = __float2bfloat16_rn(y);
    float rx = x - __bfloat162float(hx), ry = y - __bfloat162float(hy);
    __nv_bfloat16 lx = __float2bfloat16_rn(rx), ly = __float2bfloat16_rn(ry);
    hi = ((uint32_t)__bfloat16_as_ushort(hy) << 16) | (uint32_t)__bfloat16_as_ushort(hx);
    lo = ((uint32_t)__bfloat16_as_ushort(ly) << 16) | (uint32_t)__bfloat16_as_ushort(lx);
}
__device__ __forceinline__ void acc4(float4& a, const float4& v0, const float4& v1,
                                     const float4& v2, const float4& v3) {
    a.x += (v0.x + v1.x) + (v2.x + v3.x);
    a.y += (v0.y + v1.y) + (v2.y + v3.y);
    a.z += (v0.z + v1.z) + (v2.z + v3.z);
    a.w += (v0.w + v1.w) + (v2.w + v3.w);
}

// ---------------------------------------------------------------------------
// Edge dtype detection + fused convert/histogram
// ---------------------------------------------------------------------------
__global__ void detect_dtype(const int* __restrict__ buf) {
    if (threadIdx.x == 0 && blockIdx.x == 0) {
        int any = 0;
        for (int i = 1; i < 256; i += 2) any |= buf[i];
        g_is64 = (any == 0) ? 1 : 0;
    }
}

__global__ void zero_int2(int N) {
    int i = blockIdx.x * blockDim.x + threadIdx.x;
    if (i < N) { g_cnt[i] = 0; g_fill[i] = 0; }
}

__global__ void convert_hist(const void* __restrict__ ei, int E, int N) {
    int e = blockIdx.x * blockDim.x + threadIdx.x;
    if (e >= E) return;
    int s, t;
    if (g_is64) {
        const long long* p = (const long long*)ei;
        s = (int)p[e]; t = (int)p[e + E];
    } else {
        const int* p = (const int*)ei;
        s = p[e]; t = p[e + E];
    }
    g_src[e] = s;
    g_tgt[e] = t;
    if ((unsigned)t < (unsigned)N) atomicAdd(&g_cnt[t], 1);
}

// ---------------------------------------------------------------------------
// multi-block scan: rowptr[i+1] = sum cnt[0..i]
// ---------------------------------------------------------------------------
__global__ void scan_partials(int n) {
    __shared__ int sh[1024];
    int i = blockIdx.x * 1024 + threadIdx.x;
    sh[threadIdx.x] = (i < n) ? g_cnt[i] : 0;
    __syncthreads();
    for (int off = 1; off < 1024; off <<= 1) {
        int t = (threadIdx.x >= (unsigned)off) ? sh[threadIdx.x - off] : 0;
        __syncthreads();
        sh[threadIdx.x] += t;
        __syncthreads();
    }
    if (i < n) g_rowptr[i + 1] = sh[threadIdx.x];
    if (threadIdx.x == 1023) g_blk[blockIdx.x] = sh[1023];
}

__global__ void scan_blocks(int nb) {
    if (threadIdx.x == 0 && blockIdx.x == 0) {
        int s = 0;
        for (int b = 0; b < nb; b++) { int t = g_blk[b]; g_blk[b] = s; s += t; }
        g_rowptr[0] = 0;
    }
}

__global__ void add_offsets(int n) {
    int i = blockIdx.x * 1024 + threadIdx.x;
    if (i < n) g_rowptr[i + 1] += g_blk[blockIdx.x];
}

__global__ void build_csr(int E, int N) {
    int e = blockIdx.x * blockDim.x + threadIdx.x;
    if (e < E) {
        int t = g_tgt[e];
        int s = g_src[e];
        if ((unsigned)t < (unsigned)N && (unsigned)s < (unsigned)N) {
            int pos = g_rowptr[t] + atomicAdd(&g_fill[t], 1);
            if ((unsigned)pos < (unsigned)MAX_EDGES) g_csr[pos] = s;
        }
    }
}

// ---------------------------------------------------------------------------
// fused weights, transposed to [o][k], split into bf16 hi/lo
// ---------------------------------------------------------------------------
__global__ void fuse_weights_t(const float* __restrict__ w1, const float* __restrict__ c1,
                               const float* __restrict__ w2, const float* __restrict__ c2) {
    int idx = blockIdx.x * blockDim.x + threadIdx.x;
    const int T1 = 384 * 128;
    const int T2 = 384 * 64;
    if (idx < T1) {
        int k = idx >> 7, o = idx & 127;
        int i = k & 127, p = k >> 7;
        float v = 0.1f * c1[(i * 128 + o) * 3 + p];
        if (p == 0) v += w1[i * 128 + o];
        __nv_bfloat16 h = __float2bfloat16_rn(v);
        g_w1hi[o * 384 + k] = h;
        g_w1lo[o * 384 + k] = __float2bfloat16_rn(v - __bfloat162float(h));
    } else if (idx < T1 + T2) {
        int j = idx - T1;
        int k = j >> 6, o = j & 63;
        int i = k & 127, p = k >> 7;
        float v = 0.1f * c2[(i * 64 + o) * 3 + p];
        if (p == 0) v += w2[i * 64 + o];
        __nv_bfloat16 h = __float2bfloat16_rn(v);
        g_w2hi[o * 384 + k] = h;
        g_w2lo[o * 384 + k] = __float2bfloat16_rn(v - __bfloat162float(h));
    }
}

// ---------------------------------------------------------------------------
// mma.sync bf16x2 GEMM: Out[128-tile x BN] = Aug(X)[tile x 384] @ Weff + bias.
// BK=32, double-buffered SMEM (pad-8 bf16 rows), 8 warps = 4(M) x 2(N).
// acc += Ahi*Bhi + Ahi*Blo + Alo*Bhi (fp32 accumulate in MMA).
// ---------------------------------------------------------------------------
template <int BN>
__global__ void __launch_bounds__(256) kan_gemm_mma(const float* __restrict__ Xp,
                                                    const float* __restrict__ bias, int N) {
    const int NT = BN / 16;                       // n8-tiles per warp
    const uint32_t ASZ = 128 * 40 * 2;            // bf16 tile, stride 40
    const uint32_t BSZ = (uint32_t)BN * 40 * 2;
    const uint32_t AHo = 0, BHo = 2 * ASZ;
    const uint32_t SBUF = 2 * ASZ + 2 * BSZ;

    extern __shared__ __align__(128) char smem[];
    uint32_t sb = smem_u32(smem);
    int tid = threadIdx.x, lane = tid & 31, wid = tid >> 5;
    int warp_m = wid & 3, warp_n = wid >> 2;
    int rowBase = blockIdx.x * 128;

    const float4* X4 = (BN == 128) ? (const float4*)Xp : g_a1;
    const __nv_bfloat16* WHp = (BN == 128) ? g_w1hi : g_w2hi;
    const __nv_bfloat16* WLp = (BN == 128) ? g_w1lo : g_w2lo;
    float* Out = (BN == 128) ? (float*)g_h1 : (float*)g_h2;

    // ---- producer indexing: thread -> (row, 16-col half) ----
    int rowl = tid >> 1, half = tid & 1;
    int nrow = rowBase + rowl;
    bool bact = rowl < BN;

    float4 xa[4];
    uint4 wh0, wh1, wl0, wl1;

    auto loadA = [&](int c) {
        int p = c >> 2;
        int i0 = (c & 3) * 32 + half * 16;
        if (nrow < N) {
            const float4* ptr = X4 + (size_t)nrow * 32 + (i0 >> 2);
            xa[0] = ptr[0]; xa[1] = ptr[1]; xa[2] = ptr[2]; xa[3] = ptr[3];
        } else {
            xa[0] = xa[1] = xa[2] = xa[3] = make_float4(0.f, 0.f, 0.f, 0.f);
        }
        if (p == 1) {
#pragma unroll
            for (int j = 0; j < 4; j++) {
                xa[j].x *= xa[j].x; xa[j].y *= xa[j].y;
                xa[j].z *= xa[j].z; xa[j].w *= xa[j].w;
            }
        } else if (p == 2) {
#pragma unroll
            for (int j = 0; j < 4; j++) {
                xa[j].x = xa[j].x * xa[j].x * xa[j].x;
                xa[j].y = xa[j].y * xa[j].y * xa[j].y;
                xa[j].z = xa[j].z * xa[j].z * xa[j].z;
                xa[j].w = xa[j].w * xa[j].w * xa[j].w;
            }
        }
    };
    auto loadB = [&](int c) {
        if (!bact) return;
        size_t off = (size_t)rowl * 384 + c * 32 + half * 16;
        wh0 = *(const uint4*)(WHp + off); wh1 = *(const uint4*)(WHp + off + 8);
        wl0 = *(const uint4*)(WLp + off); wl1 = *(const uint4*)(WLp + off + 8);
    };
    auto sts = [&](int buf) {
        char* abase = smem + buf * SBUF + AHo + rowl * 80 + half * 32;
#pragma unroll
        for (int j = 0; j < 4; j++) {
            uint32_t h0, l0, h1, l1;
            split2(xa[j].x, xa[j].y, h0, l0);
            split2(xa[j].z, xa[j].w, h1, l1);
            *(uint2*)(abase + j * 8) = make_uint2(h0, h1);
            *(uint2*)(abase + ASZ + j * 8) = make_uint2(l0, l1);
        }
        if (bact) {
            char* bbase = smem + buf * SBUF + BHo + rowl * 80 + half * 32;
            *(uint4*)(bbase) = wh0;
            *(uint4*)(bbase + 16) = wh1;
            *(uint4*)(bbase + BSZ) = wl0;
            *(uint4*)(bbase + BSZ + 16) = wl1;
        }
    };

    // ---- consumer: ldmatrix lane offsets ----
    int lr = lane & 7, ls = lane >> 3;
    int a_row = lr + ((ls & 1) << 3);
    int a_k = (ls >> 1) << 3;
    int b_row = lr + ((ls >> 1) << 3);
    int b_k = (ls & 1) << 3;

    float acc[2][NT][4];
#pragma unroll
    for (int i = 0; i < 2; i++)
#pragma unroll
        for (int j = 0; j < NT; j++)
#pragma unroll
            for (int q = 0; q < 4; q++) acc[i][j][q] = 0.f;

    auto compute = [&](int buf) {
        uint32_t base = sb + buf * SBUF;
#pragma unroll
        for (int ks = 0; ks < 32; ks += 16) {
            uint32_t ah[2][4], al[2][4];
#pragma unroll
            for (int i = 0; i < 2; i++) {
                uint32_t ad = base + AHo + (uint32_t)(warp_m * 32 + i * 16 + a_row) * 80 +
                              (uint32_t)(ks + a_k) * 2;
                ldsm4(ah[i], ad);
                ldsm4(al[i], ad + ASZ);
            }
            uint32_t bh[NT][2], bl[NT][2];
#pragma unroll
            for (int j2 = 0; j2 < NT / 2; j2++) {
                uint32_t bd = base + BHo +
                              (uint32_t)(warp_n * (BN / 2) + j2 * 16 + b_row) * 80 +
                              (uint32_t)(ks + b_k) * 2;
                uint32_t t[4];
                ldsm4(t, bd);
                bh[2 * j2][0] = t[0]; bh[2 * j2][1] = t[1];
                bh[2 * j2 + 1][0] = t[2]; bh[2 * j2 + 1][1] = t[3];
                ldsm4(t, bd + BSZ);
                bl[2 * j2][0] = t[0]; bl[2 * j2][1] = t[1];
                bl[2 * j2 + 1][0] = t[2]; bl[2 * j2 + 1][1] = t[3];
            }
#pragma unroll
            for (int i = 0; i < 2; i++)
#pragma unroll
                for (int j = 0; j < NT; j++) {
                    mma16816(acc[i][j], ah[i], bh[j]);
                    mma16816(acc[i][j], ah[i], bl[j]);
                    mma16816(acc[i][j], al[i], bh[j]);
                }
        }
    };

    // ---- pipelined main loop over 12 K-chunks ----
    loadA(0); loadB(0);
    for (int c = 0; c < 12; c++) {
        int buf = c & 1;
        sts(buf);
        __syncthreads();
        if (c < 11) { loadA(c + 1); loadB(c + 1); }
        compute(buf);
        __syncthreads();
    }

    // ---- epilogue: bias (+relu), float2 stores ----
    int g = lane >> 2, t4 = lane & 3;
#pragma unroll
    for (int i = 0; i < 2; i++) {
        int m0 = rowBase + warp_m * 32 + i * 16 + g;
#pragma unroll
        for (int j = 0; j < NT; j++) {
            int col = warp_n * (BN / 2) + j * 8 + t4 * 2;
            float bx = bias[col], by = bias[col + 1];
            float v0 = acc[i][j][0] + bx, v1 = acc[i][j][1] + by;
            float v2 = acc[i][j][2] + bx, v3 = acc[i][j][3] + by;
            if (BN == 128) {
                v0 = fmaxf(v0, 0.f); v1 = fmaxf(v1, 0.f);
                v2 = fmaxf(v2, 0.f); v3 = fmaxf(v3, 0.f);
            }
            if (m0 < N) *(float2*)(Out + (size_t)m0 * BN + col) = make_float2(v0, v1);
            if (m0 + 8 < N) *(float2*)(Out + (size_t)(m0 + 8) * BN + col) = make_float2(v2, v3);
        }
    }
}

// ---------------------------------------------------------------------------
// gather-mean 1 (unroll-4, MLP=4): g_a1[n][:] = mean_{s in nbrs(n)} g_h1[s][:]
// ---------------------------------------------------------------------------
__global__ void gather_mean1(int N) {
    int g = blockIdx.x * 8 + ((int)threadIdx.x >> 5);
    int lane = (int)threadIdx.x & 31;
    if (g >= N) return;
    int beg = g_rowptr[g], end = g_rowptr[g + 1];
    float4 acc = make_float4(0.f, 0.f, 0.f, 0.f);
    int e = beg;
    for (; e + 4 <= end; e += 4) {
        int s0 = g_csr[e], s1 = g_csr[e + 1], s2 = g_csr[e + 2], s3 = g_csr[e + 3];
        float4 v0 = g_h1[(size_t)s0 * 32 + lane];
        float4 v1 = g_h1[(size_t)s1 * 32 + lane];
        float4 v2 = g_h1[(size_t)s2 * 32 + lane];
        float4 v3 = g_h1[(size_t)s3 * 32 + lane];
        acc4(acc, v0, v1, v2, v3);
    }
    for (; e < end; e++) {
        float4 v = g_h1[(size_t)g_csr[e] * 32 + lane];
        acc.x += v.x; acc.y += v.y; acc.z += v.z; acc.w += v.w;
    }
    float inv = 1.f / (float)max(end - beg, 1);
    acc.x *= inv; acc.y *= inv; acc.z *= inv; acc.w *= inv;
    g_a1[(size_t)g * 32 + lane] = acc;
}

// gather-mean 2 + log_softmax over 64 features; 16-lane group per node.
__global__ void gather_mean_lsm(float4* __restrict__ Out, int N) {
    int g = blockIdx.x * 16 + ((int)threadIdx.x >> 4);
    int lane = (int)threadIdx.x & 15;
    if (g >= N) return;
    int beg = g_rowptr[g], end = g_rowptr[g + 1];
    float4 acc = make_float4(0.f, 0.f, 0.f, 0.f);
    int e = beg;
    for (; e + 4 <= end; e += 4) {
        int s0 = g_csr[e], s1 = g_csr[e + 1], s2 = g_csr[e + 2], s3 = g_csr[e + 3];
        float4 v0 = g_h2[(size_t)s0 * 16 + lane];
        float4 v1 = g_h2[(size_t)s1 * 16 + lane];
        float4 v2 = g_h2[(size_t)s2 * 16 + lane];
        float4 v3 = g_h2[(size_t)s3 * 16 + lane];
        acc4(acc, v0, v1, v2, v3);
    }
    for (; e < end; e++) {
        float4 v = g_h2[(size_t)g_csr[e] * 16 + lane];
        acc.x += v.x; acc.y += v.y; acc.z += v.z; acc.w += v.w;
    }
    float inv = 1.f / (float)max(end - beg, 1);
    acc.x *= inv; acc.y *= inv; acc.z *= inv; acc.w *= inv;

    float m = fmaxf(fmaxf(acc.x, acc.y), fmaxf(acc.z, acc.w));
#pragma unroll
    for (int off = 8; off; off >>= 1) m = fmaxf(m, __shfl_xor_sync(0xffffffffu, m, off));
    float s = expf(acc.x - m) + expf(acc.y - m) + expf(acc.z - m) + expf(acc.w - m);
#pragma unroll
    for (int off = 8; off; off >>= 1) s += __shfl_xor_sync(0xffffffffu, s, off);
    float lse = m + logf(s);
    acc.x -= lse; acc.y -= lse; acc.z -= lse; acc.w -= lse;
    Out[(size_t)g * 16 + lane] = acc;
}

// ---------------------------------------------------------------------------
extern "C" void kernel_launch(void* const* d_in, const int* in_sizes, int n_in,
                              void* d_out, int out_size) {
    const float* x  = (const float*)d_in[0];
    const void*  ei = d_in[1];
    const float* w1 = (const float*)d_in[2];
    const float* b1 = (const float*)d_in[3];
    const float* c1 = (const float*)d_in[4];
    const float* w2 = (const float*)d_in[5];
    const float* b2 = (const float*)d_in[6];
    const float* c2 = (const float*)d_in[7];
    float4* out     = (float4*)d_out;

    int N = in_sizes[0] / 128;
    int E = in_sizes[1] / 2;

    const int SMEM1 = 2 * (2 * 10240 + 2 * 128 * 80);  // 81920
    const int SMEM2 = 2 * (2 * 10240 + 2 * 64 * 80);   // 61440
    cudaFuncSetAttribute(kan_gemm_mma<128>, cudaFuncAttributeMaxDynamicSharedMemorySize, SMEM1);
    cudaFuncSetAttribute(kan_gemm_mma<64>,  cudaFuncAttributeMaxDynamicSharedMemorySize, SMEM2);

    // fork-join: CSR build on side stream, weights+GEMM1 on main (capture) stream.
    // Stream/events are created per call and deliberately NOT destroyed here:
    // destroying a stream that participates in an active capture invalidates it.
    cudaStream_t s1;
    cudaStreamCreateWithFlags(&s1, cudaStreamNonBlocking);
    cudaEvent_t evF, evJ;
    cudaEventCreateWithFlags(&evF, cudaEventDisableTiming);
    cudaEventCreateWithFlags(&evJ, cudaEventDisableTiming);

    cudaEventRecord(evF, 0);
    cudaStreamWaitEvent(s1, evF, 0);

    // CSR chain (side stream)
    zero_int2<<<(N + 255) / 256, 256, 0, s1>>>(N);
    detect_dtype<<<1, 32, 0, s1>>>((const int*)ei);
    convert_hist<<<(E + 255) / 256, 256, 0, s1>>>(ei, E, N);
    int nb = (N + 1023) / 1024;
    scan_partials<<<nb, 1024, 0, s1>>>(N);
    scan_blocks<<<1, 32, 0, s1>>>(nb);
    add_offsets<<<nb, 1024, 0, s1>>>(N);
    build_csr<<<(E + 255) / 256, 256, 0, s1>>>(E, N);
    cudaEventRecord(evJ, s1);

    // weights + layer 1 (main stream, overlapped with CSR chain)
    fuse_weights_t<<<(384 * 128 + 384 * 64 + 255) / 256, 256>>>(w1, c1, w2, c2);
    int tiles = (N + 127) / 128;
    kan_gemm_mma<128><<<tiles, 256, SMEM1>>>(x, b1, N);

    // join: gathers need both CSR and h1
    cudaStreamWaitEvent(0, evJ, 0);

    // aggregate 1 (mean)
    gather_mean1<<<(N + 7) / 8, 256>>>(N);

    // layer 2
    kan_gemm_mma<64><<<tiles, 256, SMEM2>>>(nullptr, b2, N);

    // aggregate 2 (mean) + log_softmax, straight into d_out
    gather_mean_lsm<<<(N + 15) / 16, 256>>>(out, N);
}